// round 14
// baseline (speedup 1.0000x reference)
#include <cuda_runtime.h>
#include <cuda_fp16.h>
#include <math.h>
#include <stdint.h>

#define BB 256
#define TT 512
#define HH 512
#define G4 2048
#define LSC 1024.0f

// ---- device images (static; no allocation anywhere) ----
__device__ uint4 g_ximg [(size_t)TT * 2 * 1024];     // [t][half] : 4 ki * 4KB = 16KB
__device__ uint4 g_W1img[(size_t)32 * 16384];        // [gt] : 64 ki * (2KB hi + 2KB lo)
__device__ uint4 g_W0img[(size_t)32 * 9216];         // [gt] : 36 ki * 4KB
__device__ uint4 g_h0img[(size_t)2 * 2 * 8192];      // [slot][half] : 32 ki * 4KB
__device__ uint4 g_h1img[(size_t)2 * 2 * 8192];
__device__ float g_b0[G4], g_b1[G4];
__device__ float g_h1last[BB * HH];
__device__ float g_part[64 * 256 * 32];              // [pair][tid][frag] split-K partials (2MB)
__device__ unsigned g_pflag[64];                     // per-pair cumulative flags
__device__ unsigned g_cnt[2];

__device__ __forceinline__ float sg(float x) { return __fdividef(1.0f, 1.0f + __expf(-x)); }
__device__ __forceinline__ float th(float x) { return 1.0f - __fdividef(2.0f, __expf(2.0f * x) + 1.0f); }

__device__ __forceinline__ unsigned fpk2(float a, float b) {
    __half2 h = __floats2half2_rn(a, b);
    return *reinterpret_cast<unsigned*>(&h);
}
__device__ __forceinline__ void wsplit2(float a, float b, unsigned& hi, unsigned& lo) {
    __half ha = __float2half_rn(a), hb = __float2half_rn(b);
    float ra = (a - __half2float(ha)) * LSC;
    float rb = (b - __half2float(hb)) * LSC;
    hi = (unsigned)__half_as_ushort(ha) | ((unsigned)__half_as_ushort(hb) << 16);
    lo = fpk2(ra, rb);
}

#define MMA(c, a, bx, by) \
    asm volatile("mma.sync.aligned.m16n8k16.row.col.f32.f16.f16.f32 " \
        "{%0,%1,%2,%3}, {%4,%5,%6,%7}, {%8,%9}, {%0,%1,%2,%3};" \
        : "+f"((c)[0]), "+f"((c)[1]), "+f"((c)[2]), "+f"((c)[3]) \
        : "r"((a).x), "r"((a).y), "r"((a).z), "r"((a).w), "r"(bx), "r"(by))

// =================== pack: build fragment-exact images (proven) ===================
__global__ void pack_kernel(const float* __restrict__ x,
    const float* __restrict__ wi0, const float* __restrict__ wh0,
    const float* __restrict__ bi0, const float* __restrict__ bh0,
    const float* __restrict__ wi1, const float* __restrict__ wh1,
    const float* __restrict__ bi1, const float* __restrict__ bh1)
{
    const long long stride = (long long)gridDim.x * blockDim.x;
    const long long t0 = (long long)blockIdx.x * blockDim.x + threadIdx.x;
    if (t0 == 0) { g_cnt[0] = 0u; g_cnt[1] = 0u; }
    for (long long i = t0; i < 64; i += stride) g_pflag[i] = 0u;
    for (long long i = t0; i < G4; i += stride) { g_b0[i] = bi0[i] + bh0[i]; g_b1[i] = bi1[i] + bh1[i]; }
    uint4 z = make_uint4(0, 0, 0, 0);
    for (long long i = t0; i < 2 * 2 * 8192; i += stride) { g_h0img[i] = z; g_h1img[i] = z; }

    // ---- x image (fp16 single plane)
    for (long long i = t0; i < (long long)TT * 2 * 4 * 8 * 32; i += stride) {
        int lane = (int)(i & 31), mi = (int)((i >> 5) & 7), ki = (int)((i >> 8) & 3);
        int half = (int)((i >> 10) & 1), t = (int)(i >> 11);
        int r0 = mi * 16 + (lane >> 2), k0 = ki * 16 + (lane & 3) * 2;
        const float* xb = x + ((size_t)(half * 128 + r0) * TT + t) * 64;
        const float* xb8 = xb + (size_t)8 * TT * 64;
        uint4 hi;
        hi.x = fpk2(xb [k0],     xb [k0 + 1]);
        hi.y = fpk2(xb8[k0],     xb8[k0 + 1]);
        hi.z = fpk2(xb [k0 + 8], xb [k0 + 9]);
        hi.w = fpk2(xb8[k0 + 8], xb8[k0 + 9]);
        char* dst = (char*)g_ximg + ((size_t)t * 2 + half) * 16384 + ki * 4096 + (mi * 32 + lane) * 16;
        *(uint4*)dst = hi;
    }

    // ---- W1 image
    for (long long i = t0; i < (long long)32 * 64 * 32 * 4; i += stride) {
        int p = (int)(i & 3), lane = (int)((i >> 2) & 31), ki = (int)((i >> 7) & 63), gt = (int)(i >> 13);
        int j0 = p * 16 + (lane >> 2), j1 = j0 + 8;
        int k0 = ki * 16 + (lane & 3) * 2;
        int G0 = (j0 & 3) * 512 + gt * 16 + (j0 >> 2);
        int G1 = (j1 & 3) * 512 + gt * 16 + (j1 >> 2);
        const float* s00 = (k0 < 512)     ? wi1 + (size_t)G0 * 512 + k0     : wh1 + (size_t)G0 * 512 + k0 - 512;
        const float* s08 = (k0 + 8 < 512) ? wi1 + (size_t)G0 * 512 + k0 + 8 : wh1 + (size_t)G0 * 512 + k0 + 8 - 512;
        const float* s10 = (k0 < 512)     ? wi1 + (size_t)G1 * 512 + k0     : wh1 + (size_t)G1 * 512 + k0 - 512;
        const float* s18 = (k0 + 8 < 512) ? wi1 + (size_t)G1 * 512 + k0 + 8 : wh1 + (size_t)G1 * 512 + k0 + 8 - 512;
        uint4 hi, lo;
        wsplit2(s00[0], s00[1], hi.x, lo.x);
        wsplit2(s08[0], s08[1], hi.y, lo.y);
        wsplit2(s10[0], s10[1], hi.z, lo.z);
        wsplit2(s18[0], s18[1], hi.w, lo.w);
        char* dst = (char*)g_W1img + (size_t)gt * 262144 + ki * 4096 + (p * 32 + lane) * 16;
        *(uint4*)dst = hi; *(uint4*)(dst + 2048) = lo;
    }

    // ---- W0 image: K = 576 -> 36 ki
    for (long long i = t0; i < (long long)32 * 36 * 32 * 4; i += stride) {
        int p = (int)(i & 3), lane = (int)((i >> 2) & 31);
        int rem = (int)(i >> 7); int ki = rem % 36, gt = rem / 36;
        int j0 = p * 16 + (lane >> 2), j1 = j0 + 8;
        int k0 = ki * 16 + (lane & 3) * 2;
        int G0 = (j0 & 3) * 512 + gt * 16 + (j0 >> 2);
        int G1 = (j1 & 3) * 512 + gt * 16 + (j1 >> 2);
        const float* s00 = (k0 < 64)     ? wi0 + (size_t)G0 * 64 + k0     : wh0 + (size_t)G0 * 512 + k0 - 64;
        const float* s08 = (k0 + 8 < 64) ? wi0 + (size_t)G0 * 64 + k0 + 8 : wh0 + (size_t)G0 * 512 + k0 + 8 - 64;
        const float* s10 = (k0 < 64)     ? wi0 + (size_t)G1 * 64 + k0     : wh0 + (size_t)G1 * 512 + k0 - 64;
        const float* s18 = (k0 + 8 < 64) ? wi0 + (size_t)G1 * 64 + k0 + 8 : wh0 + (size_t)G1 * 512 + k0 + 8 - 64;
        uint4 hi, lo;
        wsplit2(s00[0], s00[1], hi.x, lo.x);
        wsplit2(s08[0], s08[1], hi.y, lo.y);
        wsplit2(s10[0], s10[1], hi.z, lo.z);
        wsplit2(s18[0], s18[1], hi.w, lo.w);
        char* dst = (char*)g_W0img + (size_t)gt * 147456 + ki * 4096 + (p * 32 + lane) * 16;
        *(uint4*)dst = hi; *(uint4*)(dst + 2048) = lo;
    }
}

// =================== grid barrier (cumulative, 2 domains of 64 CTAs) ===================
__device__ __forceinline__ void gbar(int dom, unsigned& tgt)
{
    __syncthreads();
    if (threadIdx.x == 0) {
        __threadfence();
        tgt += 64;
        atomicAdd(&g_cnt[dom], 1u);
        while (*(volatile unsigned*)&g_cnt[dom] < tgt) { }
        __threadfence();
    }
    __syncthreads();
}

// =================== one layer-step: W from SMEM, 4-stage A prefetch, split-K ===================
__device__ void stepH(const char* __restrict__ aA, int nA,
                      const char* __restrict__ aB, int nB,
                      const uint4* __restrict__ wS,
                      const float* __restrict__ bs, float* creg,
                      char* hImg, float* hlastBase, int gt, float (*Ds)[68],
                      float* pOut, const float* pIn,
                      volatile unsigned* flag, unsigned ftgt)
{
    const int tid = threadIdx.x, lane = tid & 31;
    const int wz = (tid >> 5) & 3;
    const int wg = tid >> 7;
    const int nCh = nA + nB;             // always divisible by 4
    float acc[2][4][4];
    #pragma unroll
    for (int m = 0; m < 2; m++)
        #pragma unroll
        for (int n = 0; n < 4; n++)
            #pragma unroll
            for (int q = 0; q < 4; q++) acc[m][n][q] = 0.f;

    uint4 ahA[2], ahB[2], ahC[2], ahD[2];
    uint4 whA[2], whB[2];
    const int wb0 = (wg * 2) * 32 + lane, wb1 = (wg * 2 + 1) * 32 + lane;

#define LDA(S, c) do { \
    const char* ab_ = ((c) < nA) ? aA + (size_t)(c) * 4096 : aB + (size_t)((c) - nA) * 4096; \
    const char* pa_ = ab_ + ((wz * 2) * 32 + lane) * 16; \
    ah##S[0] = *(const uint4*)pa_; \
    ah##S[1] = *(const uint4*)(pa_ + 512); \
} while (0)

#define LDW(S, c) do { \
    wh##S[0] = wS[(c) * 128 + wb0]; \
    wh##S[1] = wS[(c) * 128 + wb1]; \
} while (0)

#define MMAC(S, T) do { \
    _Pragma("unroll") \
    for (int m_ = 0; m_ < 2; m_++) \
        _Pragma("unroll") \
        for (int p_ = 0; p_ < 2; p_++) { \
            MMA(acc[m_][2*p_],   ah##S[m_], wh##T[p_].x, wh##T[p_].y); \
            MMA(acc[m_][2*p_+1], ah##S[m_], wh##T[p_].z, wh##T[p_].w); \
        } \
} while (0)

    LDA(A, 0); LDA(B, 1); LDA(C, 2);
    LDW(A, 0);
    for (int c = 0; c < nCh; c += 4) {
        LDA(D, c + 3);                LDW(B, c + 1);                 MMAC(A, A);
        if (c + 4 < nCh) LDA(A, c + 4); LDW(A, c + 2);               MMAC(B, B);
        if (c + 5 < nCh) LDA(B, c + 5); LDW(B, c + 3);               MMAC(C, A);
        if (c + 6 < nCh) LDA(C, c + 6); if (c + 4 < nCh) LDW(A, c + 4); MMAC(D, B);
    }
#undef LDA
#undef LDW
#undef MMAC

    // ---- split-K producer: store partial fragments and return ----
    if (pOut) {
        float4* po = (float4*)pOut + tid * 8;
        #pragma unroll
        for (int m = 0; m < 2; m++)
            #pragma unroll
            for (int n = 0; n < 4; n++)
                po[m * 4 + n] = make_float4(acc[m][n][0], acc[m][n][1], acc[m][n][2], acc[m][n][3]);
        return;   // caller: __syncthreads + fence + flag
    }
    // ---- split-K consumer: wait for partial, add ----
    if (pIn) {
        if (tid == 0) { while (*flag < ftgt) { } __threadfence(); }
        __syncthreads();
        const float4* pi = (const float4*)pIn + tid * 8;
        #pragma unroll
        for (int m = 0; m < 2; m++)
            #pragma unroll
            for (int n = 0; n < 4; n++) {
                float4 v = pi[m * 4 + n];
                acc[m][n][0] += v.x; acc[m][n][1] += v.y;
                acc[m][n][2] += v.z; acc[m][n][3] += v.w;
            }
    }

    // ---- stage D to SMEM (row-major) ----
    #pragma unroll
    for (int m = 0; m < 2; m++)
        #pragma unroll
        for (int n = 0; n < 4; n++) {
            int r0 = wz * 32 + m * 16 + (lane >> 2);
            int c0 = (wg * 4 + n) * 8 + (lane & 3) * 2;
            Ds[r0][c0]     = acc[m][n][0];
            Ds[r0][c0 + 1] = acc[m][n][1];
            Ds[r0 + 8][c0]     = acc[m][n][2];
            Ds[r0 + 8][c0 + 1] = acc[m][n][3];
        }
    __syncthreads();

    // ---- gate math: thread owns row tid>>1, unit-half tid&1 (8 units) ----
    const int r  = tid >> 1;
    const int uh = tid & 1;
    float h[8];
    #pragma unroll
    for (int i = 0; i < 8; i++) {
        int ul = uh * 8 + i;
        float gi = sg(Ds[r][4*ul + 0] + bs[4*ul + 0]);
        float gf = sg(Ds[r][4*ul + 1] + bs[4*ul + 1]);
        float gg = th(Ds[r][4*ul + 2] + bs[4*ul + 2]);
        float go = sg(Ds[r][4*ul + 3] + bs[4*ul + 3]);
        float cc = gf * creg[i] + gi * gg;
        creg[i] = cc;
        h[i] = go * th(cc);
    }

    if (hImg) {
        int rl = r & 15, mi = r >> 4;
        char* base = hImg + gt * 4096 + mi * 512;
        #pragma unroll
        for (int j = 0; j < 4; j++) {
            unsigned hi32 = fpk2(h[2*j], h[2*j + 1]);
            int lane2 = (rl & 7) * 4 + j;
            int p4 = (rl >> 3) + 2 * uh;
            *(unsigned*)(base + lane2 * 16 + p4 * 4) = hi32;
        }
    }
    if (hlastBase) {
        float* dst = hlastBase + (size_t)r * HH + gt * 16 + uh * 8;
        #pragma unroll
        for (int i = 0; i < 8; i++) dst[i] = h[i];
    }
    __syncthreads();
}

// =================== persistent recurrence ===================
__global__ __launch_bounds__(256, 1) void lstm_persistent()
{
    extern __shared__ uint4 wS[];
    __shared__ float Ds[128][68];
    __shared__ float bs[64];
    const int tid = threadIdx.x, cta = blockIdx.x;
    const int lyr  = cta >> 6;          // 0: layer1 worker, 1: layer0 worker
    const int half = (cta >> 5) & 1;
    const int gt   = cta & 31;
    const int pair = half * 32 + gt;
    float* pbuf = g_part + (size_t)pair * 8192;

    // ---- stage W into SMEM ----
    if (lyr == 0) {
        // layer1 worker: W1 chunks 0..51 (hi planes)
        const uint4* wsrc = g_W1img + (size_t)gt * 16384;
        for (int j = tid; j < 52 * 128; j += 256)
            wS[j] = wsrc[(size_t)(j >> 7) * 256 + (j & 127)];
    } else {
        // layer0 worker: W0 chunks 0..35 at [0..36*128), W1 chunks 52..63 at [36*128..48*128)
        const uint4* w0src = g_W0img + (size_t)gt * 9216;
        for (int j = tid; j < 36 * 128; j += 256)
            wS[j] = w0src[(size_t)(j >> 7) * 256 + (j & 127)];
        const uint4* w1src = g_W1img + (size_t)gt * 16384;
        for (int j = tid; j < 12 * 128; j += 256)
            wS[36 * 128 + j] = w1src[(size_t)(52 + (j >> 7)) * 256 + (j & 127)];
    }

    const float* bias = lyr ? g_b0 : g_b1;
    if (tid < 64) bs[tid] = bias[(tid & 3) * 512 + gt * 16 + (tid >> 2)];
    __syncthreads();

    float creg[8];
    #pragma unroll
    for (int i = 0; i < 8; i++) creg[i] = 0.f;
    unsigned tgt = 0u;

    #define XI(t)  ((char*)g_ximg  + ((size_t)(t) * 2 + half) * 16384)
    #define H0I(s) ((char*)g_h0img + ((size_t)((s) * 2 + half)) * 131072)
    #define H1I(s) ((char*)g_h1img + ((size_t)((s) * 2 + half)) * 131072)

    // prologue: layer0(t=0) reads h0 slot1 (zeros), writes slot0
    if (lyr == 1)
        stepH(XI(0), 4, H0I(1), 32, wS, bs, creg, H0I(0), nullptr, gt, Ds,
              nullptr, nullptr, nullptr, 0u);
    gbar(half, tgt);

    for (int p = 0; p < TT - 1; p++) {
        const int s = p & 1;
        if (lyr == 0) {
            // layer1(p): K chunks 0..51 (h0 all 32 + h1 chunks 0..19), combine tail partial
            stepH(H0I(s), 32, H1I(s ^ 1), 20, wS, bs, creg, H1I(s), nullptr, gt, Ds,
                  nullptr, pbuf, &g_pflag[pair], (unsigned)(p + 1));
        } else {
            // tail partial of layer1(p): K chunks 52..63 = h1 chunks 20..31
            stepH(H1I(s ^ 1) + 20 * 4096, 12, H1I(s ^ 1) + 20 * 4096, 0, wS + 36 * 128,
                  bs, creg, nullptr, nullptr, gt, Ds, pbuf, nullptr, nullptr, 0u);
            __syncthreads();
            if (tid == 0) { __threadfence(); atomicAdd(&g_pflag[pair], 1u); }
            // layer0(p+1)
            stepH(XI(p + 1), 4, H0I(s), 32, wS, bs, creg, H0I(s ^ 1), nullptr, gt, Ds,
                  nullptr, nullptr, nullptr, 0u);
        }
        gbar(half, tgt);
    }

    // final phase p=511 (s=1): layer1(511) with split-K
    if (lyr == 1) {
        stepH(H1I(0) + 20 * 4096, 12, H1I(0) + 20 * 4096, 0, wS + 36 * 128,
              bs, creg, nullptr, nullptr, gt, Ds, pbuf, nullptr, nullptr, 0u);
        __syncthreads();
        if (tid == 0) { __threadfence(); atomicAdd(&g_pflag[pair], 1u); }
    } else {
        stepH(H0I(1), 32, H1I(0), 20, wS, bs, creg, nullptr,
              g_h1last + (size_t)half * 128 * HH, gt, Ds,
              nullptr, pbuf, &g_pflag[pair], 512u);
    }
}

// =================== final FC ===================
__global__ void fc_kernel(const float* __restrict__ fc_w, const float* __restrict__ fc_b,
                          float* __restrict__ out)
{
    const int b = blockIdx.x;
    const float* h = g_h1last + (size_t)b * HH;
    float s = 0.f;
    for (int k = threadIdx.x; k < HH; k += 128) s += h[k] * fc_w[k];
    #pragma unroll
    for (int off = 16; off > 0; off >>= 1) s += __shfl_xor_sync(0xffffffffu, s, off);
    __shared__ float ws[4];
    if ((threadIdx.x & 31) == 0) ws[threadIdx.x >> 5] = s;
    __syncthreads();
    if (threadIdx.x == 0) out[b] = ws[0] + ws[1] + ws[2] + ws[3] + fc_b[0];
}

extern "C" void kernel_launch(void* const* d_in, const int* in_sizes, int n_in,
                              void* d_out, int out_size)
{
    const float* x   = (const float*)d_in[0];
    const float* wi0 = (const float*)d_in[1];
    const float* wh0 = (const float*)d_in[2];
    const float* bi0 = (const float*)d_in[3];
    const float* bh0 = (const float*)d_in[4];
    const float* wi1 = (const float*)d_in[5];
    const float* wh1 = (const float*)d_in[6];
    const float* bi1 = (const float*)d_in[7];
    const float* bh1 = (const float*)d_in[8];
    const float* fcw = (const float*)d_in[9];
    const float* fcb = (const float*)d_in[10];
    float* out = (float*)d_out;

    static int smem_set = 0;
    if (!smem_set) {
        cudaFuncSetAttribute(lstm_persistent,
                             cudaFuncAttributeMaxDynamicSharedMemorySize, 52 * 2048);
        smem_set = 1;
    }

    pack_kernel<<<1024, 256>>>(x, wi0, wh0, bi0, bh0, wi1, wh1, bi1, bh1);
    lstm_persistent<<<128, 256, 52 * 2048>>>();
    fc_kernel<<<BB, 128>>>(fcw, fcb, out);
}

// round 17
// speedup vs baseline: 1.6273x; 1.6273x over previous
#include <cuda_runtime.h>
#include <cuda_fp16.h>
#include <math.h>
#include <stdint.h>

#define BB 256
#define TT 512
#define HH 512
#define G4 2048
#define LSC 1024.0f

// ---- device images (static; no allocation anywhere) ----
__device__ uint4 g_ximg [(size_t)TT * 2 * 1024];     // [t][half] : 4 ki * 4KB = 16KB
__device__ uint4 g_W1img[(size_t)32 * 16384];        // [gt] : 64 ki * (2KB hi + 2KB lo)
__device__ uint4 g_W0img[(size_t)32 * 9216];         // [gt] : 36 ki * 4KB
__device__ uint4 g_h0img[(size_t)2 * 2 * 8192];      // [slot][half] : 32 ki * 4KB
__device__ uint4 g_h1img[(size_t)2 * 2 * 8192];
__device__ float g_b0[G4], g_b1[G4];
__device__ float g_h1last[BB * HH];
__device__ unsigned g_cnt[2];

__device__ __forceinline__ float sg(float x) { return __fdividef(1.0f, 1.0f + __expf(-x)); }
__device__ __forceinline__ float th(float x) { return 1.0f - __fdividef(2.0f, __expf(2.0f * x) + 1.0f); }

__device__ __forceinline__ unsigned fpk2(float a, float b) {
    __half2 h = __floats2half2_rn(a, b);
    return *reinterpret_cast<unsigned*>(&h);
}
__device__ __forceinline__ void wsplit2(float a, float b, unsigned& hi, unsigned& lo) {
    __half ha = __float2half_rn(a), hb = __float2half_rn(b);
    float ra = (a - __half2float(ha)) * LSC;
    float rb = (b - __half2float(hb)) * LSC;
    hi = (unsigned)__half_as_ushort(ha) | ((unsigned)__half_as_ushort(hb) << 16);
    lo = fpk2(ra, rb);
}

#define MMA(c, a, bx, by) \
    asm volatile("mma.sync.aligned.m16n8k16.row.col.f32.f16.f16.f32 " \
        "{%0,%1,%2,%3}, {%4,%5,%6,%7}, {%8,%9}, {%0,%1,%2,%3};" \
        : "+f"((c)[0]), "+f"((c)[1]), "+f"((c)[2]), "+f"((c)[3]) \
        : "r"((a).x), "r"((a).y), "r"((a).z), "r"((a).w), "r"(bx), "r"(by))

// =================== pack: build fragment-exact images (proven) ===================
__global__ void pack_kernel(const float* __restrict__ x,
    const float* __restrict__ wi0, const float* __restrict__ wh0,
    const float* __restrict__ bi0, const float* __restrict__ bh0,
    const float* __restrict__ wi1, const float* __restrict__ wh1,
    const float* __restrict__ bi1, const float* __restrict__ bh1)
{
    const long long stride = (long long)gridDim.x * blockDim.x;
    const long long t0 = (long long)blockIdx.x * blockDim.x + threadIdx.x;
    if (t0 == 0) { g_cnt[0] = 0u; g_cnt[1] = 0u; }
    for (long long i = t0; i < G4; i += stride) { g_b0[i] = bi0[i] + bh0[i]; g_b1[i] = bi1[i] + bh1[i]; }
    uint4 z = make_uint4(0, 0, 0, 0);
    for (long long i = t0; i < 2 * 2 * 8192; i += stride) { g_h0img[i] = z; g_h1img[i] = z; }

    // ---- x image (fp16 single plane)
    for (long long i = t0; i < (long long)TT * 2 * 4 * 8 * 32; i += stride) {
        int lane = (int)(i & 31), mi = (int)((i >> 5) & 7), ki = (int)((i >> 8) & 3);
        int half = (int)((i >> 10) & 1), t = (int)(i >> 11);
        int r0 = mi * 16 + (lane >> 2), k0 = ki * 16 + (lane & 3) * 2;
        const float* xb = x + ((size_t)(half * 128 + r0) * TT + t) * 64;
        const float* xb8 = xb + (size_t)8 * TT * 64;
        uint4 hi;
        hi.x = fpk2(xb [k0],     xb [k0 + 1]);
        hi.y = fpk2(xb8[k0],     xb8[k0 + 1]);
        hi.z = fpk2(xb [k0 + 8], xb [k0 + 9]);
        hi.w = fpk2(xb8[k0 + 8], xb8[k0 + 9]);
        char* dst = (char*)g_ximg + ((size_t)t * 2 + half) * 16384 + ki * 4096 + (mi * 32 + lane) * 16;
        *(uint4*)dst = hi;
    }

    // ---- W1 image
    for (long long i = t0; i < (long long)32 * 64 * 32 * 4; i += stride) {
        int p = (int)(i & 3), lane = (int)((i >> 2) & 31), ki = (int)((i >> 7) & 63), gt = (int)(i >> 13);
        int j0 = p * 16 + (lane >> 2), j1 = j0 + 8;
        int k0 = ki * 16 + (lane & 3) * 2;
        int G0 = (j0 & 3) * 512 + gt * 16 + (j0 >> 2);
        int G1 = (j1 & 3) * 512 + gt * 16 + (j1 >> 2);
        const float* s00 = (k0 < 512)     ? wi1 + (size_t)G0 * 512 + k0     : wh1 + (size_t)G0 * 512 + k0 - 512;
        const float* s08 = (k0 + 8 < 512) ? wi1 + (size_t)G0 * 512 + k0 + 8 : wh1 + (size_t)G0 * 512 + k0 + 8 - 512;
        const float* s10 = (k0 < 512)     ? wi1 + (size_t)G1 * 512 + k0     : wh1 + (size_t)G1 * 512 + k0 - 512;
        const float* s18 = (k0 + 8 < 512) ? wi1 + (size_t)G1 * 512 + k0 + 8 : wh1 + (size_t)G1 * 512 + k0 + 8 - 512;
        uint4 hi, lo;
        wsplit2(s00[0], s00[1], hi.x, lo.x);
        wsplit2(s08[0], s08[1], hi.y, lo.y);
        wsplit2(s10[0], s10[1], hi.z, lo.z);
        wsplit2(s18[0], s18[1], hi.w, lo.w);
        char* dst = (char*)g_W1img + (size_t)gt * 262144 + ki * 4096 + (p * 32 + lane) * 16;
        *(uint4*)dst = hi; *(uint4*)(dst + 2048) = lo;
    }

    // ---- W0 image: K = 576 -> 36 ki
    for (long long i = t0; i < (long long)32 * 36 * 32 * 4; i += stride) {
        int p = (int)(i & 3), lane = (int)((i >> 2) & 31);
        int rem = (int)(i >> 7); int ki = rem % 36, gt = rem / 36;
        int j0 = p * 16 + (lane >> 2), j1 = j0 + 8;
        int k0 = ki * 16 + (lane & 3) * 2;
        int G0 = (j0 & 3) * 512 + gt * 16 + (j0 >> 2);
        int G1 = (j1 & 3) * 512 + gt * 16 + (j1 >> 2);
        const float* s00 = (k0 < 64)     ? wi0 + (size_t)G0 * 64 + k0     : wh0 + (size_t)G0 * 512 + k0 - 64;
        const float* s08 = (k0 + 8 < 64) ? wi0 + (size_t)G0 * 64 + k0 + 8 : wh0 + (size_t)G0 * 512 + k0 + 8 - 64;
        const float* s10 = (k0 < 64)     ? wi0 + (size_t)G1 * 64 + k0     : wh0 + (size_t)G1 * 512 + k0 - 64;
        const float* s18 = (k0 + 8 < 64) ? wi0 + (size_t)G1 * 64 + k0 + 8 : wh0 + (size_t)G1 * 512 + k0 + 8 - 64;
        uint4 hi, lo;
        wsplit2(s00[0], s00[1], hi.x, lo.x);
        wsplit2(s08[0], s08[1], hi.y, lo.y);
        wsplit2(s10[0], s10[1], hi.z, lo.z);
        wsplit2(s18[0], s18[1], hi.w, lo.w);
        char* dst = (char*)g_W0img + (size_t)gt * 147456 + ki * 4096 + (p * 32 + lane) * 16;
        *(uint4*)dst = hi; *(uint4*)(dst + 2048) = lo;
    }
}

// =================== grid barrier (cumulative, 2 domains of 64 CTAs) ===================
__device__ __forceinline__ void gbar(int dom, unsigned& tgt)
{
    __syncthreads();
    if (threadIdx.x == 0) {
        __threadfence();
        tgt += 64;
        atomicAdd(&g_cnt[dom], 1u);
        while (*(volatile unsigned*)&g_cnt[dom] < tgt) { }
        __threadfence();
    }
    __syncthreads();
}

// =================== one layer-step: W from SMEM, 8-deep A prefetch (consume-then-load) ===================
__device__ void stepH(const char* __restrict__ aA, int nA,
                      const char* __restrict__ aB, int nB,
                      const uint4* __restrict__ wS,      // SMEM W (hi planes, 128 uint4/chunk)
                      const float* __restrict__ bs, float* creg,
                      char* hImg, float* hlastBase, int gt, float (*Ds)[68])
{
    const int tid = threadIdx.x, lane = tid & 31;
    const int wz = (tid >> 5) & 3;       // row slice 0..3
    const int wg = tid >> 7;             // col half 0..1
    const int nCh = nA + nB;             // 36 or 64 (nCh % 8 == 4 or 0; nCh > 8)
    float acc[2][4][4];
    #pragma unroll
    for (int m = 0; m < 2; m++)
        #pragma unroll
        for (int n = 0; n < 4; n++)
            #pragma unroll
            for (int q = 0; q < 4; q++) acc[m][n][q] = 0.f;

    uint4 ah0[2], ah1[2], ah2[2], ah3[2], ah4[2], ah5[2], ah6[2], ah7[2];
    uint4 whA[2], whB[2];
    const int wb0 = (wg * 2) * 32 + lane, wb1 = (wg * 2 + 1) * 32 + lane;

#define LDA(S, c) do { \
    const char* ab_ = ((c) < nA) ? aA + (size_t)(c) * 4096 : aB + (size_t)((c) - nA) * 4096; \
    const char* pa_ = ab_ + ((wz * 2) * 32 + lane) * 16; \
    ah##S[0] = *(const uint4*)pa_; \
    ah##S[1] = *(const uint4*)(pa_ + 512); \
} while (0)

#define LDW(S, c) do { \
    wh##S[0] = wS[(c) * 128 + wb0]; \
    wh##S[1] = wS[(c) * 128 + wb1]; \
} while (0)

#define MMAC(S, T) do { \
    _Pragma("unroll") \
    for (int m_ = 0; m_ < 2; m_++) \
        _Pragma("unroll") \
        for (int p_ = 0; p_ < 2; p_++) { \
            MMA(acc[m_][2*p_],   ah##S[m_], wh##T[p_].x, wh##T[p_].y); \
            MMA(acc[m_][2*p_+1], ah##S[m_], wh##T[p_].z, wh##T[p_].w); \
        } \
} while (0)

    // preload 8 A chunks (nCh >= 36 > 8)
    LDA(0, 0); LDA(1, 1); LDA(2, 2); LDA(3, 3);
    LDA(4, 4); LDA(5, 5); LDA(6, 6); LDA(7, 7);
    LDW(A, 0);

    // CRITICAL ORDER: consume buffer S (MMAC) BEFORE refilling it (LDA S, c+8)
    int c = 0;
    for (; c + 8 <= nCh; c += 8) {
        LDW(B, c + 1);                   MMAC(0, A);  if (c + 8  < nCh) LDA(0, c + 8);
        LDW(A, c + 2);                   MMAC(1, B);  if (c + 9  < nCh) LDA(1, c + 9);
        LDW(B, c + 3);                   MMAC(2, A);  if (c + 10 < nCh) LDA(2, c + 10);
        LDW(A, c + 4);                   MMAC(3, B);  if (c + 11 < nCh) LDA(3, c + 11);
        LDW(B, c + 5);                   MMAC(4, A);  if (c + 12 < nCh) LDA(4, c + 12);
        LDW(A, c + 6);                   MMAC(5, B);  if (c + 13 < nCh) LDA(5, c + 13);
        LDW(B, c + 7);                   MMAC(6, A);  if (c + 14 < nCh) LDA(6, c + 14);
        if (c + 8 < nCh) LDW(A, c + 8);  MMAC(7, B);  if (c + 15 < nCh) LDA(7, c + 15);
    }
    if (c < nCh) {   // tail of 4 (nCh % 8 == 4): chunks c..c+3 sit in ah0..ah3, whA = chunk c
        LDW(B, c + 1); MMAC(0, A);
        LDW(A, c + 2); MMAC(1, B);
        LDW(B, c + 3); MMAC(2, A);
        MMAC(3, B);
    }
#undef LDA
#undef LDW
#undef MMAC

    // ---- stage D to SMEM (row-major) ----
    #pragma unroll
    for (int m = 0; m < 2; m++)
        #pragma unroll
        for (int n = 0; n < 4; n++) {
            int r0 = wz * 32 + m * 16 + (lane >> 2);
            int c0 = (wg * 4 + n) * 8 + (lane & 3) * 2;
            Ds[r0][c0]     = acc[m][n][0];
            Ds[r0][c0 + 1] = acc[m][n][1];
            Ds[r0 + 8][c0]     = acc[m][n][2];
            Ds[r0 + 8][c0 + 1] = acc[m][n][3];
        }
    __syncthreads();

    // ---- gate math: thread owns row tid>>1, unit-half tid&1 (8 units) ----
    const int r  = tid >> 1;
    const int uh = tid & 1;
    float h[8];
    #pragma unroll
    for (int i = 0; i < 8; i++) {
        int ul = uh * 8 + i;
        float gi = sg(Ds[r][4*ul + 0] + bs[4*ul + 0]);
        float gf = sg(Ds[r][4*ul + 1] + bs[4*ul + 1]);
        float gg = th(Ds[r][4*ul + 2] + bs[4*ul + 2]);
        float go = sg(Ds[r][4*ul + 3] + bs[4*ul + 3]);
        float cc = gf * creg[i] + gi * gg;
        creg[i] = cc;
        h[i] = go * th(cc);
    }

    if (hImg) {   // write h as fp16 A-fragments at ki = gt (single plane)
        int rl = r & 15, mi = r >> 4;
        char* base = hImg + gt * 4096 + mi * 512;
        #pragma unroll
        for (int j = 0; j < 4; j++) {
            unsigned hi32 = fpk2(h[2*j], h[2*j + 1]);
            int lane2 = (rl & 7) * 4 + j;
            int p4 = (rl >> 3) + 2 * uh;
            *(unsigned*)(base + lane2 * 16 + p4 * 4) = hi32;
        }
    }
    if (hlastBase) {
        float* dst = hlastBase + (size_t)r * HH + gt * 16 + uh * 8;
        #pragma unroll
        for (int i = 0; i < 8; i++) dst[i] = h[i];
    }
    __syncthreads();
}

// =================== persistent recurrence ===================
__global__ __launch_bounds__(256, 1) void lstm_persistent()
{
    extern __shared__ uint4 wS[];          // staged W hi-planes (<=128KB)
    __shared__ float Ds[128][68];
    __shared__ float bs[64];
    const int tid = threadIdx.x, cta = blockIdx.x;
    const int lyr  = cta >> 6;          // 0: layer1 worker, 1: layer0 worker
    const int half = (cta >> 5) & 1;
    const int gt   = cta & 31;

    // ---- stage this CTA's W (hi plane only) into SMEM once ----
    const uint4* wsrc = lyr ? (g_W0img + (size_t)gt * 9216) : (g_W1img + (size_t)gt * 16384);
    const int nWc = lyr ? 36 : 64;
    for (int j = tid; j < nWc * 128; j += 256)
        wS[j] = wsrc[(size_t)(j >> 7) * 256 + (j & 127)];

    const float* bias = lyr ? g_b0 : g_b1;
    if (tid < 64) bs[tid] = bias[(tid & 3) * 512 + gt * 16 + (tid >> 2)];
    __syncthreads();

    float creg[8];
    #pragma unroll
    for (int i = 0; i < 8; i++) creg[i] = 0.f;
    unsigned tgt = 0u;

    #define XI(t)  ((char*)g_ximg  + ((size_t)(t) * 2 + half) * 16384)
    #define H0I(s) ((char*)g_h0img + ((size_t)((s) * 2 + half)) * 131072)
    #define H1I(s) ((char*)g_h1img + ((size_t)((s) * 2 + half)) * 131072)

    // prologue: layer0(t=0) reads h0 slot1 (zeros), writes slot0
    if (lyr == 1)
        stepH(XI(0), 4, H0I(1), 32, wS, bs, creg, H0I(0), nullptr, gt, Ds);
    gbar(half, tgt);

    for (int p = 0; p < TT - 1; p++) {
        const int s = p & 1;
        if (lyr == 0)   // layer1(p): A = h0(slot s) || h1(slot s^1); writes h1 slot s
            stepH(H0I(s), 32, H1I(s ^ 1), 32, wS, bs, creg, H1I(s), nullptr, gt, Ds);
        else            // layer0(p+1): A = x(p+1) || h0(slot s); writes h0 slot s^1
            stepH(XI(p + 1), 4, H0I(s), 32, wS, bs, creg, H0I(s ^ 1), nullptr, gt, Ds);
        gbar(half, tgt);
    }

    // layer1(511): A = h0 slot1 || h1 slot0 ; fp32 output only
    if (lyr == 0)
        stepH(H0I(1), 32, H1I(0), 32, wS, bs, creg, nullptr,
              g_h1last + (size_t)half * 128 * HH, gt, Ds);
}

// =================== final FC ===================
__global__ void fc_kernel(const float* __restrict__ fc_w, const float* __restrict__ fc_b,
                          float* __restrict__ out)
{
    const int b = blockIdx.x;
    const float* h = g_h1last + (size_t)b * HH;
    float s = 0.f;
    for (int k = threadIdx.x; k < HH; k += 128) s += h[k] * fc_w[k];
    #pragma unroll
    for (int off = 16; off > 0; off >>= 1) s += __shfl_xor_sync(0xffffffffu, s, off);
    __shared__ float ws[4];
    if ((threadIdx.x & 31) == 0) ws[threadIdx.x >> 5] = s;
    __syncthreads();
    if (threadIdx.x == 0) out[b] = ws[0] + ws[1] + ws[2] + ws[3] + fc_b[0];
}

extern "C" void kernel_launch(void* const* d_in, const int* in_sizes, int n_in,
                              void* d_out, int out_size)
{
    const float* x   = (const float*)d_in[0];
    const float* wi0 = (const float*)d_in[1];
    const float* wh0 = (const float*)d_in[2];
    const float* bi0 = (const float*)d_in[3];
    const float* bh0 = (const float*)d_in[4];
    const float* wi1 = (const float*)d_in[5];
    const float* wh1 = (const float*)d_in[6];
    const float* bi1 = (const float*)d_in[7];
    const float* bh1 = (const float*)d_in[8];
    const float* fcw = (const float*)d_in[9];
    const float* fcb = (const float*)d_in[10];
    float* out = (float*)d_out;

    static int smem_set = 0;
    if (!smem_set) {
        cudaFuncSetAttribute(lstm_persistent,
                             cudaFuncAttributeMaxDynamicSharedMemorySize, 131072);
        smem_set = 1;
    }

    pack_kernel<<<1024, 256>>>(x, wi0, wh0, bi0, bh0, wi1, wh1, bi1, bh1);
    lstm_persistent<<<128, 256, 131072>>>();
    fc_kernel<<<BB, 128>>>(fcw, fcb, out);
}